// round 1
// baseline (speedup 1.0000x reference)
#include <cuda_runtime.h>
#include <cuda_bf16.h>

// PhysicsRouter: logits = X @ W^T + mass*bias; softmax; top-2; aux loss.
// Shapes: X [16384, 4096] f32, mass [16384], W [4, 4096], bias [4].
// Output layout (f32, reference return order, flattened):
//   [0              , 65536)  logits        [N, 4]
//   [65536          , 98304)  top_k_indices [N, 2] (as float)
//   [98304          , 98305)  aux_loss      scalar
//   [98305          , 131073) top_k_weights [N, 2]

#define C_DIM 4096
#define E_DIM 4
#define N_TOK 16384
#define GROUP 16                 // tokens per warp
#define WARPS_PER_BLOCK 4
#define BLOCK_THREADS (WARPS_PER_BLOCK * 32)
#define GRID_BLOCKS (N_TOK / (GROUP * WARPS_PER_BLOCK))   // 256

__device__ double g_imp[E_DIM];  // expert importance accumulator

__global__ void zero_kernel() {
    if (threadIdx.x < E_DIM) g_imp[threadIdx.x] = 0.0;
}

__global__ __launch_bounds__(BLOCK_THREADS)
void router_main(const float* __restrict__ X,
                 const float* __restrict__ mass,
                 const float* __restrict__ W,
                 const float* __restrict__ bias,
                 float* __restrict__ out)
{
    const int warp  = blockIdx.x * WARPS_PER_BLOCK + (threadIdx.x >> 5);
    const int lane  = threadIdx.x & 31;
    const long token0 = (long)warp * GROUP;

    float acc[GROUP][E_DIM];
#pragma unroll
    for (int t = 0; t < GROUP; t++)
#pragma unroll
        for (int e = 0; e < E_DIM; e++) acc[t][e] = 0.0f;

    // Main loop: 32 iterations, 128 columns per warp per iteration.
    // Gate float4s are loaded once per iteration and reused across 16 tokens.
#pragma unroll 1
    for (int it = 0; it < C_DIM / 128; ++it) {
        const int col = it * 128 + lane * 4;
        const float4 g0 = __ldg((const float4*)(W + 0 * C_DIM + col));
        const float4 g1 = __ldg((const float4*)(W + 1 * C_DIM + col));
        const float4 g2 = __ldg((const float4*)(W + 2 * C_DIM + col));
        const float4 g3 = __ldg((const float4*)(W + 3 * C_DIM + col));
#pragma unroll
        for (int t = 0; t < GROUP; t++) {
            const float4 x = __ldg((const float4*)(X + (token0 + t) * C_DIM + col));
            acc[t][0] = fmaf(x.x, g0.x, fmaf(x.y, g0.y, fmaf(x.z, g0.z, fmaf(x.w, g0.w, acc[t][0]))));
            acc[t][1] = fmaf(x.x, g1.x, fmaf(x.y, g1.y, fmaf(x.z, g1.z, fmaf(x.w, g1.w, acc[t][1]))));
            acc[t][2] = fmaf(x.x, g2.x, fmaf(x.y, g2.y, fmaf(x.z, g2.z, fmaf(x.w, g2.w, acc[t][2]))));
            acc[t][3] = fmaf(x.x, g3.x, fmaf(x.y, g3.y, fmaf(x.z, g3.z, fmaf(x.w, g3.w, acc[t][3]))));
        }
    }

    // Warp butterfly reduce all 64 accumulators; every lane ends with full sums.
#pragma unroll
    for (int t = 0; t < GROUP; t++)
#pragma unroll
        for (int e = 0; e < E_DIM; e++)
#pragma unroll
            for (int s = 16; s > 0; s >>= 1)
                acc[t][e] += __shfl_xor_sync(0xFFFFFFFFu, acc[t][e], s);

    // Select this lane's token (lane t handles token0 + t), static-index only.
    float l[E_DIM] = {0.f, 0.f, 0.f, 0.f};
#pragma unroll
    for (int t = 0; t < GROUP; t++) {
        if (lane == t) {
#pragma unroll
            for (int e = 0; e < E_DIM; e++) l[e] = acc[t][e];
        }
    }

    float p[E_DIM] = {0.f, 0.f, 0.f, 0.f};

    if (lane < GROUP) {
        const long token = token0 + lane;
        const float m = __ldg(mass + token);
        const float4 b = __ldg((const float4*)bias);
        l[0] = fmaf(m, b.x, l[0]);
        l[1] = fmaf(m, b.y, l[1]);
        l[2] = fmaf(m, b.z, l[2]);
        l[3] = fmaf(m, b.w, l[3]);

        // logits
        float4 lo; lo.x = l[0]; lo.y = l[1]; lo.z = l[2]; lo.w = l[3];
        *(float4*)(out + token * E_DIM) = lo;

        // softmax (max-subtract, matches jax.nn.softmax)
        const float mx = fmaxf(fmaxf(l[0], l[1]), fmaxf(l[2], l[3]));
        p[0] = expf(l[0] - mx);
        p[1] = expf(l[1] - mx);
        p[2] = expf(l[2] - mx);
        p[3] = expf(l[3] - mx);
        const float inv = 1.0f / (p[0] + p[1] + p[2] + p[3]);
        p[0] *= inv; p[1] *= inv; p[2] *= inv; p[3] *= inv;

        // top-2 with lowest-index tie break (strict > keeps earlier index)
        int i1 = 0; float v1 = p[0];
#pragma unroll
        for (int e = 1; e < E_DIM; e++) {
            if (p[e] > v1) { v1 = p[e]; i1 = e; }
        }
        int i2 = -1; float v2 = -1.0f;
#pragma unroll
        for (int e = 0; e < E_DIM; e++) {
            if (e != i1 && p[e] > v2) { v2 = p[e]; i2 = e; }
        }

        float* out_idx = out + (long)N_TOK * E_DIM;
        float* out_w   = out + (long)N_TOK * E_DIM + (long)N_TOK * 2 + 1;
        out_idx[token * 2 + 0] = (float)i1;
        out_idx[token * 2 + 1] = (float)i2;
        out_w[token * 2 + 0]   = v1;
        out_w[token * 2 + 1]   = v2;
    }

    // Warp-level importance reduction (lanes >= GROUP contribute zeros).
#pragma unroll
    for (int e = 0; e < E_DIM; e++)
#pragma unroll
        for (int s = 16; s > 0; s >>= 1)
            p[e] += __shfl_xor_sync(0xFFFFFFFFu, p[e], s);

    if (lane == 0) {
#pragma unroll
        for (int e = 0; e < E_DIM; e++)
            atomicAdd(&g_imp[e], (double)p[e]);
    }
}

__global__ void finalize_kernel(float* __restrict__ out) {
    if (threadIdx.x == 0 && blockIdx.x == 0) {
        const double target = (double)N_TOK / (double)E_DIM;
        double s = 0.0;
#pragma unroll
        for (int e = 0; e < E_DIM; e++) {
            const double d = g_imp[e] - target;
            s += d * d;
        }
        out[(long)N_TOK * E_DIM + (long)N_TOK * 2] = (float)(s / E_DIM);
    }
}

extern "C" void kernel_launch(void* const* d_in, const int* in_sizes, int n_in,
                              void* d_out, int out_size)
{
    const float* X    = (const float*)d_in[0];
    const float* mass = (const float*)d_in[1];
    const float* W    = (const float*)d_in[2];
    const float* bias = (const float*)d_in[3];
    float* out = (float*)d_out;

    zero_kernel<<<1, 32>>>();
    router_main<<<GRID_BLOCKS, BLOCK_THREADS>>>(X, mass, W, bias, out);
    finalize_kernel<<<1, 32>>>(out);
}